// round 6
// baseline (speedup 1.0000x reference)
#include <cuda_runtime.h>
#include <math.h>

#define Bsz   1024
#define Nn    32
#define SP    60
#define SE    10
#define OOUT  5
#define IIN   6
#define GPB   8      // samples per block
#define TPB   192    // 180 active: gate g in {0,1,2} x dim k in [0,60)

// ---- shared memory layout (float offsets; all 16B-aligned) ----
#define S_WIH 0        // 10800 (staging Whh first, then permanent Wih)
#define S_WF  10800    // 60 rows x 84 = 5040
#define S_BF  15840    // 60
#define S_HAS 15900    // 8*32 = 256
#define S_ZD  16156    // 8*20 = 160
#define S_H   16320    // 8*64 = 512
#define S_R   16832    // 512
#define S_Z   17344    // 512
#define S_GIN 17856    // 512
#define S_GHN 18368    // 512
#define S_RHO 18880    // 512
#define SMEM_FLOATS 19392   // 77568 B

// ---- device scratch ----
__device__ int   g_fcnt[Nn];
__device__ int   g_flist[Nn][Nn];
__device__ int   g_bcnt[Nn];
__device__ int   g_blist[Nn][Nn];
__device__ float g_rho_f[Nn * Bsz * SP];
__device__ float g_rho_b[Nn * Bsz * SP];
__device__ float g_af[Bsz * SP];
__device__ float g_ab[Bsz * SP];
__device__ float g_gi_f[Nn * Bsz * 180];   // gi cache incl. bih: [node][b][row]
__device__ float g_gi_b[Nn * Bsz * 180];

// ============================================================
// packed f32x2 helpers
// ============================================================
__device__ __forceinline__ unsigned long long pk2(float a, float b) {
    unsigned long long v;
    asm("mov.b64 %0,{%1,%2};" : "=l"(v) : "f"(a), "f"(b));
    return v;
}
__device__ __forceinline__ float2 unpk2(unsigned long long v) {
    float2 f;
    asm("mov.b64 {%0,%1},%2;" : "=f"(f.x), "=f"(f.y) : "l"(v));
    return f;
}

__device__ __forceinline__ float sigmf_(float x) {
    return __fdividef(1.0f, 1.0f + __expf(-x));
}
__device__ __forceinline__ float tanhsafe_(float x) {
    float a = fabsf(x);
    float e = __expf(-2.0f * a);
    float t = __fdividef(1.0f - e, 1.0f + e);
    return copysignf(t, x);
}

// GEMV over sH (8 samples x 60) with register wpk row; gv[b] = init[b] + row.h[b]
__device__ __forceinline__ void gemv_packed(unsigned hbase,
                                            const unsigned long long* wpk,
                                            const float* init, float* gv) {
    unsigned long long acc[GPB];
    #pragma unroll
    for (int b = 0; b < GPB; b++) acc[b] = pk2(init[b], 0.0f);
    #pragma unroll
    for (int q = 0; q < 15; q++) {
        #pragma unroll
        for (int b = 0; b < GPB; b++) {
            unsigned long long h01, h23;
            asm("ld.shared.v2.u64 {%0,%1},[%2];"
                : "=l"(h01), "=l"(h23) : "r"(hbase + b * 256 + q * 16));
            asm("fma.rn.f32x2 %0,%1,%2,%0;" : "+l"(acc[b]) : "l"(wpk[2*q]),   "l"(h01));
            asm("fma.rn.f32x2 %0,%1,%2,%0;" : "+l"(acc[b]) : "l"(wpk[2*q+1]), "l"(h23));
        }
    }
    #pragma unroll
    for (int b = 0; b < GPB; b++) { float2 f = unpk2(acc[b]); gv[b] = f.x + f.y; }
}

// ============================================================
// Prep: decode adj + build ordered edge lists
// ============================================================
__global__ void k_prep(const unsigned char* __restrict__ adj_raw) {
    __shared__ float sadj[Nn * Nn];
    __shared__ int s_gt1, s_off4;
    const int tid = threadIdx.x;
    if (tid == 0) { s_gt1 = 0; s_off4 = 0; }
    __syncthreads();
    int f_gt1 = 0, f_off4 = 0;
    for (int t = tid; t < Nn * Nn; t += blockDim.x) {
        unsigned char c = adj_raw[t];
        if (c > 1) f_gt1 = 1;
        if (c == 1 && (t & 3) != 0) f_off4 = 1;
    }
    if (f_gt1)  atomicOr(&s_gt1, 1);
    if (f_off4) atomicOr(&s_off4, 1);
    __syncthreads();
    const int mode = s_gt1 ? 1 : (s_off4 ? 0 : 2);
    for (int e = tid; e < Nn * Nn; e += blockDim.x) {
        float v;
        if (mode == 1)      v = ((const float*)adj_raw)[e];
        else if (mode == 2) v = (float)(((const int*)adj_raw)[e]);
        else                v = (float)adj_raw[e];
        sadj[e] = v;
    }
    __syncthreads();
    if (tid < Nn) {
        const int i = tid; int c = 0;
        for (int j = 0; j < Nn; j++)
            if (sadj[j * Nn + i] != 0.0f) g_flist[i][c++] = j;
        g_fcnt[i] = c;
    } else if (tid < 2 * Nn) {
        const int i = tid - Nn; int c = 0;
        for (int j = Nn - 1; j >= 0; j--)
            if (sadj[i * Nn + j] != 0.0f) g_blist[i][c++] = j;
        g_bcnt[i] = c;
    }
}

// ============================================================
// Main scan
// ============================================================
__global__ void __launch_bounds__(TPB, 2) k_scan(
    const float* __restrict__ has, const float* __restrict__ z, const float* __restrict__ dz,
    const float* __restrict__ Wih_f, const float* __restrict__ Whh_f,
    const float* __restrict__ bih_f, const float* __restrict__ bhh_f,
    const float* __restrict__ Wih_b, const float* __restrict__ Whh_b,
    const float* __restrict__ bih_b, const float* __restrict__ bhh_b,
    const float* __restrict__ Wfp, const float* __restrict__ bfp,
    const float* __restrict__ Wbp, const float* __restrict__ bbp)
{
    extern __shared__ __align__(16) float sm[];
    unsigned smem_u32;
    asm("{ .reg .u64 t; cvta.to.shared.u64 t, %1; cvt.u32.u64 %0, t; }"
        : "=r"(smem_u32) : "l"(sm));
    const unsigned hbase   = smem_u32 + S_H   * 4;
    const unsigned rhobase = smem_u32 + S_RHO * 4;
    const unsigned wihbase = smem_u32 + S_WIH * 4;

    const int dir = blockIdx.x >> 7;
    const int b0  = (blockIdx.x & 127) * GPB;
    const float* Wih = dir ? Wih_b : Wih_f;
    const float* Whh = dir ? Whh_b : Whh_f;
    const float* bih = dir ? bih_b : bih_f;
    const float* bhh = dir ? bhh_b : bhh_f;
    const float* Wp  = dir ? Wbp   : Wfp;
    const float* bp  = dir ? bbp   : bfp;
    float* grho = dir ? g_rho_b : g_rho_f;
    float* gic  = dir ? g_gi_b  : g_gi_f;

    const int  tid = threadIdx.x;
    const int  g   = tid / 60;          // 0=r, 1=z, 2=n (3 -> idle)
    const int  k   = tid - g * 60;
    const bool act = tid < 180;

    // pointwise / projection item ownership (static): items o = tid + 180*m, o<480
    int ib[3], ik[3];
    #pragma unroll
    for (int m = 0; m < 3; m++) {
        int o = tid + 180 * m;
        ib[m] = o / 60; ik[m] = o - ib[m] * 60;
    }
    const bool it2 = (tid < 120);

    // ---- stage Wf (pad 84), biases, has, Whh->S_WIH
    for (int idx = tid; idx < 4800; idx += TPB)
        sm[S_WF + (idx / 80) * 84 + (idx % 80)] = Wp[idx];
    for (int idx = tid; idx < 60; idx += TPB) sm[S_BF + idx] = bp[idx];
    for (int idx = tid; idx < 256; idx += TPB)
        sm[S_HAS + idx] = has[(size_t)(b0 + (idx >> 5)) * Nn + (idx & 31)];
    for (int idx = tid; idx < 10800; idx += TPB) sm[S_WIH + idx] = Whh[idx];
    __syncthreads();

    // ---- Whh row -> packed registers
    unsigned long long wpk[30];
    if (act) {
        #pragma unroll
        for (int q = 0; q < 30; q++) {
            float2 w2 = *(const float2*)(sm + S_WIH + tid * 60 + 2 * q);
            wpk[q] = pk2(w2.x, w2.y);
        }
    }
    __syncthreads();
    // ---- now Wih resident in smem; zero sH
    for (int idx = tid; idx < 10800; idx += TPB) sm[S_WIH + idx] = Wih[idx];
    float h_old[3] = {0.0f, 0.0f, 0.0f};
    #pragma unroll
    for (int m = 0; m < 3; m++)
        if (m < 2 || it2) sm[S_H + ib[m] * 64 + ik[m]] = 0.0f;
    const float my_bih = act ? bih[tid] : 0.0f;
    const float my_bhh = act ? bhh[tid] : 0.0f;
    __syncthreads();

    float gi_cur[GPB], gi_nxt[GPB], gv[GPB], init[GPB];

    // ================== node scan ==================
    for (int ii = 0; ii < Nn; ii++) {
        const int i = dir ? (Nn - 1 - ii) : ii;

        // stage z/dz for this node (consumed after barC)
        if (tid < 160) {
            const int b = tid / 20, cc = tid % 20;
            const size_t base = ((size_t)(b0 + b) * Nn + i) * SE;
            sm[S_ZD + tid] = (cc < SE) ? z[base + cc] : dz[base + cc - SE];
        }

        const int  cnt = dir ? g_bcnt[i] : g_fcnt[i];
        const int* lst = dir ? g_blist[i] : g_flist[i];

        if (cnt > 0) {
            if (act) {
                const int j0 = lst[0];
                #pragma unroll
                for (int b = 0; b < GPB; b++)
                    gi_cur[b] = gic[((size_t)j0 * Bsz + b0 + b) * 180 + tid];
            }
            for (int e = 0; e < cnt; e++) {
                const int j = lst[e];
                if (act) {
                    #pragma unroll
                    for (int b = 0; b < GPB; b++)
                        init[b] = (g == 2) ? my_bhh : (gi_cur[b] + my_bhh);
                    gemv_packed(hbase, wpk, init, gv);
                    if (g == 0) {
                        #pragma unroll
                        for (int b = 0; b < GPB; b++) sm[S_R + b * 64 + k] = gv[b];
                    } else if (g == 1) {
                        #pragma unroll
                        for (int b = 0; b < GPB; b++) sm[S_Z + b * 64 + k] = gv[b];
                    } else {
                        #pragma unroll
                        for (int b = 0; b < GPB; b++) {
                            sm[S_GHN + b * 64 + k] = gv[b];
                            sm[S_GIN + b * 64 + k] = gi_cur[b];
                        }
                    }
                    if (e + 1 < cnt) {
                        const int j2 = lst[e + 1];
                        #pragma unroll
                        for (int b = 0; b < GPB; b++)
                            gi_nxt[b] = gic[((size_t)j2 * Bsz + b0 + b) * 180 + tid];
                    }
                }
                __syncthreads();   // gates visible
                #pragma unroll
                for (int m = 0; m < 3; m++) {
                    if (m < 2 || it2) {
                        const int b = ib[m], kk = ik[m];
                        float r  = sigmf_(sm[S_R + b * 64 + kk]);
                        float u  = sigmf_(sm[S_Z + b * 64 + kk]);
                        float nv = tanhsafe_(sm[S_GIN + b * 64 + kk]
                                             + r * sm[S_GHN + b * 64 + kk]);
                        float ho = h_old[m];
                        float h2 = (1.0f - u) * nv + u * ho;
                        float hn = ho + sm[S_HAS + b * 32 + j] * (h2 - ho);
                        h_old[m] = hn;
                        sm[S_H + b * 64 + kk] = hn;
                    }
                }
                __syncthreads();   // sH updated
                if (act && e + 1 < cnt) {
                    #pragma unroll
                    for (int b = 0; b < GPB; b++) gi_cur[b] = gi_nxt[b];
                }
            }
        }
        __syncthreads();   // barC: sZD (+ final sH) visible

        // ---- projection
        #pragma unroll
        for (int m = 0; m < 3; m++) {
            if (m < 2 || it2) {
                const int b = ib[m], kk = ik[m];
                float acc = sm[S_BF + kk];
                const float4* wf4 = (const float4*)(sm + S_WF + kk * 84);
                const float4* hh  = (const float4*)(sm + S_H + b * 64);
                #pragma unroll
                for (int q = 0; q < 15; q++) {
                    float4 w = wf4[q], x = hh[q];
                    acc += w.x*x.x + w.y*x.y + w.z*x.z + w.w*x.w;
                }
                #pragma unroll
                for (int c = 0; c < 20; c++)
                    acc += sm[S_WF + kk * 84 + 60 + c] * sm[S_ZD + b * 20 + c];
                if (dir == 0) acc = tanhsafe_(acc);
                sm[S_RHO + b * 64 + kk] = acc;
                grho[((size_t)i * Bsz + b0 + b) * 60 + kk] = acc;
            }
        }
        __syncthreads();   // barD: sRHO visible

        // ---- gi for this node (packed over Wih x rho) + zero sH for next node
        if (act) {
            unsigned long long acc[GPB];
            #pragma unroll
            for (int b = 0; b < GPB; b++) acc[b] = pk2(my_bih, 0.0f);
            const unsigned wrow = wihbase + tid * 240;
            #pragma unroll
            for (int q = 0; q < 15; q++) {
                unsigned long long w01, w23;
                asm("ld.shared.v2.u64 {%0,%1},[%2];"
                    : "=l"(w01), "=l"(w23) : "r"(wrow + q * 16));
                #pragma unroll
                for (int b = 0; b < GPB; b++) {
                    unsigned long long r01, r23;
                    asm("ld.shared.v2.u64 {%0,%1},[%2];"
                        : "=l"(r01), "=l"(r23) : "r"(rhobase + b * 256 + q * 16));
                    asm("fma.rn.f32x2 %0,%1,%2,%0;" : "+l"(acc[b]) : "l"(w01), "l"(r01));
                    asm("fma.rn.f32x2 %0,%1,%2,%0;" : "+l"(acc[b]) : "l"(w23), "l"(r23));
                }
            }
            #pragma unroll
            for (int b = 0; b < GPB; b++) {
                float2 f = unpk2(acc[b]);
                gic[((size_t)i * Bsz + b0 + b) * 180 + tid] = f.x + f.y;
            }
        }
        #pragma unroll
        for (int m = 0; m < 3; m++) {
            if (m < 2 || it2) sm[S_H + ib[m] * 64 + ik[m]] = 0.0f;
            h_old[m] = 0.0f;
        }
        __syncthreads();   // barE
    }

    // ================== alpha scan ==================
    const int steps = dir ? IIN : OOUT;
    for (int s = 0; s < steps; s++) {
        const int i = dir ? (IIN - 1 - s) : (Nn - OOUT + s);
        if (act) {
            #pragma unroll
            for (int b = 0; b < GPB; b++)
                gi_cur[b] = gic[((size_t)i * Bsz + b0 + b) * 180 + tid];
            #pragma unroll
            for (int b = 0; b < GPB; b++)
                init[b] = (g == 2) ? my_bhh : (gi_cur[b] + my_bhh);
            gemv_packed(hbase, wpk, init, gv);
            if (g == 0) {
                #pragma unroll
                for (int b = 0; b < GPB; b++) sm[S_R + b * 64 + k] = gv[b];
            } else if (g == 1) {
                #pragma unroll
                for (int b = 0; b < GPB; b++) sm[S_Z + b * 64 + k] = gv[b];
            } else {
                #pragma unroll
                for (int b = 0; b < GPB; b++) {
                    sm[S_GHN + b * 64 + k] = gv[b];
                    sm[S_GIN + b * 64 + k] = gi_cur[b];
                }
            }
        }
        __syncthreads();
        #pragma unroll
        for (int m = 0; m < 3; m++) {
            if (m < 2 || it2) {
                const int b = ib[m], kk = ik[m];
                float r  = sigmf_(sm[S_R + b * 64 + kk]);
                float u  = sigmf_(sm[S_Z + b * 64 + kk]);
                float nv = tanhsafe_(sm[S_GIN + b * 64 + kk]
                                     + r * sm[S_GHN + b * 64 + kk]);
                float ho = h_old[m];
                float h2 = (1.0f - u) * nv + u * ho;
                float hn = ho + sm[S_HAS + b * 32 + i] * (h2 - ho);
                h_old[m] = hn;
                sm[S_H + b * 64 + kk] = hn;
            }
        }
        __syncthreads();
    }
    {
        float* ga = dir ? g_ab : g_af;
        #pragma unroll
        for (int m = 0; m < 3; m++)
            if (m < 2 || it2)
                ga[(size_t)(b0 + ib[m]) * 60 + ik[m]] = h_old[m];
    }
}

// ============================================================
// Heads: blocks [0,128) role_prob; [128,144) instr_prob + value
// out: [0,5120) instr | [5120,234496) roles | [234496,235520) value
// NOTE: every shared array reinterpreted as float4 MUST be __align__(16) —
// merged-kernel static smem packing otherwise breaks LDS.128 alignment.
// ============================================================
__global__ void k_heads(const float* __restrict__ has,
                        const float* __restrict__ Wu, const float* __restrict__ bu,
                        const float* __restrict__ Wa, const float* __restrict__ ba,
                        const float* __restrict__ Wc, const float* __restrict__ bc,
                        float* __restrict__ out)
{
    const int tid = threadIdx.x;
    if (blockIdx.x < 128) {
        __shared__ __align__(16) float sWu[7 * 120];
        __shared__ float sbu[7];
        for (int idx = tid; idx < 840; idx += blockDim.x) sWu[idx] = Wu[idx];
        if (tid < 7) sbu[tid] = bu[tid];
        __syncthreads();

        const int t = blockIdx.x * 256 + tid;
        const int b = t >> 5;
        const int n = t & 31;

        float acc[7];
        #pragma unroll
        for (int r = 0; r < 7; r++) acc[r] = sbu[r];

        const float4* rf = (const float4*)(g_rho_f + ((size_t)n * Bsz + b) * 60);
        const float4* rb = (const float4*)(g_rho_b + ((size_t)n * Bsz + b) * 60);
        #pragma unroll
        for (int q = 0; q < 15; q++) {
            float4 f = rf[q];
            #pragma unroll
            for (int r = 0; r < 7; r++) {
                float4 w = *(const float4*)(sWu + r * 120 + q * 4);
                acc[r] += w.x*f.x + w.y*f.y + w.z*f.z + w.w*f.w;
            }
        }
        #pragma unroll
        for (int q = 0; q < 15; q++) {
            float4 f = rb[q];
            #pragma unroll
            for (int r = 0; r < 7; r++) {
                float4 w = *(const float4*)(sWu + r * 120 + 60 + q * 4);
                acc[r] += w.x*f.x + w.y*f.y + w.z*f.z + w.w*f.w;
            }
        }
        const float m = has[b * Nn + n];
        float l[7], mx = -1e30f;
        #pragma unroll
        for (int r = 0; r < 7; r++) { l[r] = (m != 0.0f) ? acc[r] : -60.0f; mx = fmaxf(mx, l[r]); }
        float s = 0.0f;
        #pragma unroll
        for (int r = 0; r < 7; r++) { l[r] = __expf(l[r] - mx); s += l[r]; }
        const float inv = __fdividef(1.0f, s);
        float* ro = out + 5120;
        #pragma unroll
        for (int r = 0; r < 7; r++) ro[((size_t)b * 7 + r) * 32 + n] = l[r] * inv;
    } else {
        __shared__ __align__(16) float sWa[5 * 120];
        __shared__ __align__(16) float sWc[120];
        __shared__ float sba[5];
        __shared__ float sbc;
        for (int idx = tid; idx < 600; idx += blockDim.x) sWa[idx] = Wa[idx];
        for (int idx = tid; idx < 120; idx += blockDim.x) sWc[idx] = Wc[idx];
        if (tid < 5) sba[tid] = ba[tid];
        if (tid == 0) sbc = bc[0];
        __syncthreads();

        const int t    = (blockIdx.x - 128) * 256 + tid;
        const int b    = t >> 2;
        const int lane = t & 3;

        float acc[6];
        #pragma unroll
        for (int a = 0; a < 6; a++) acc[a] = 0.0f;

        const float4* af = (const float4*)(g_af + (size_t)b * 60);
        const float4* ab = (const float4*)(g_ab + (size_t)b * 60);
        for (int q = lane; q < 30; q += 4) {
            float4 f = (q < 15) ? af[q] : ab[q - 15];
            #pragma unroll
            for (int a = 0; a < 5; a++) {
                float4 w = *(const float4*)(sWa + a * 120 + q * 4);
                acc[a] += w.x*f.x + w.y*f.y + w.z*f.z + w.w*f.w;
            }
            float4 wc = *(const float4*)(sWc + q * 4);
            acc[5] += wc.x*f.x + wc.y*f.y + wc.z*f.z + wc.w*f.w;
        }
        #pragma unroll
        for (int off = 1; off < 4; off <<= 1) {
            #pragma unroll
            for (int a = 0; a < 6; a++)
                acc[a] += __shfl_xor_sync(0xffffffffu, acc[a], off);
        }
        if (lane == 0) {
            float l[5], mx = -1e30f;
            #pragma unroll
            for (int a = 0; a < 5; a++) { l[a] = acc[a] + sba[a]; mx = fmaxf(mx, l[a]); }
            float s = 0.0f;
            #pragma unroll
            for (int a = 0; a < 5; a++) { l[a] = __expf(l[a] - mx); s += l[a]; }
            const float inv = __fdividef(1.0f, s);
            #pragma unroll
            for (int a = 0; a < 5; a++) out[b * 5 + a] = l[a] * inv;
            out[5120 + Bsz * 7 * Nn + b] = acc[5] + sbc;   // value @ 234496
        }
    }
}

// ============================================================
extern "C" void kernel_launch(void* const* d_in, const int* in_sizes, int n_in,
                              void* d_out, int out_size)
{
    const float* has   = (const float*)d_in[0];
    const float* z     = (const float*)d_in[1];
    const float* dz    = (const float*)d_in[2];
    const unsigned char* adj = (const unsigned char*)d_in[3];
    const float* Wih_f = (const float*)d_in[4];
    const float* Whh_f = (const float*)d_in[5];
    const float* bih_f = (const float*)d_in[6];
    const float* bhh_f = (const float*)d_in[7];
    const float* Wih_b = (const float*)d_in[8];
    const float* Whh_b = (const float*)d_in[9];
    const float* bih_b = (const float*)d_in[10];
    const float* bhh_b = (const float*)d_in[11];
    const float* Wf    = (const float*)d_in[12];
    const float* bf    = (const float*)d_in[13];
    const float* Wb    = (const float*)d_in[14];
    const float* bb    = (const float*)d_in[15];
    const float* Wa    = (const float*)d_in[16];
    const float* ba    = (const float*)d_in[17];
    const float* Wc    = (const float*)d_in[18];
    const float* bc    = (const float*)d_in[19];
    const float* Wu    = (const float*)d_in[20];
    const float* bu    = (const float*)d_in[21];
    float* out = (float*)d_out;

    const size_t smem = SMEM_FLOATS * sizeof(float);   // ~76 KB
    cudaFuncSetAttribute(k_scan, cudaFuncAttributeMaxDynamicSharedMemorySize, (int)smem);

    k_prep<<<1, 256>>>(adj);
    k_scan<<<256, TPB, smem>>>(has, z, dz,
                               Wih_f, Whh_f, bih_f, bhh_f,
                               Wih_b, Whh_b, bih_b, bhh_b,
                               Wf, bf, Wb, bb);
    k_heads<<<144, 256>>>(has, Wu, bu, Wa, ba, Wc, bc, out);
}

// round 7
// speedup vs baseline: 1.2191x; 1.2191x over previous
#include <cuda_runtime.h>
#include <math.h>

#define Bsz   1024
#define Nn    32
#define SE    10
#define OOUT  5
#define IIN   6
#define GPB   8      // samples per block
#define TPB   128    // thread = (kk in [0,60) pad 64, sg in {0,1}); 4 samples each

// ---- shared memory layout (float offsets; all float4 bases 16B-aligned) ----
#define S_WHH 0        // 180 rows x 68 (conflict-free stride) = 12240
#define S_WF  12240    // 60 rows x 84 = 5040
#define S_BF  17280    // 60
#define S_BIH 17340    // 180
#define S_HAS 17520    // 8*32 = 256
#define S_ZD  17776    // 8*20 = 160
#define S_H   17936    // 2 x 8 x 64 = 1024 (ping-pong)
#define S_RHO 18960    // 8*64 = 512
#define SMEM_FLOATS 19472   // 77888 B -> 2 blocks/SM

// ---- device scratch ----
__device__ int   g_fcnt[Nn];
__device__ int   g_flist[Nn][Nn];
__device__ int   g_bcnt[Nn];
__device__ int   g_blist[Nn][Nn];
__device__ float g_rho_f[Nn * Bsz * 60];
__device__ float g_rho_b[Nn * Bsz * 60];
__device__ float g_af[Bsz * 60];
__device__ float g_ab[Bsz * 60];
__device__ float g_gi_f[Nn * Bsz * 180];   // gi cache incl. bih: [node][b][row]
__device__ float g_gi_b[Nn * Bsz * 180];

__device__ __forceinline__ float sigmf_(float x) {
    return __fdividef(1.0f, 1.0f + __expf(-x));
}
__device__ __forceinline__ float tanhsafe_(float x) {
    float a = fabsf(x);
    float e = __expf(-2.0f * a);
    float t = __fdividef(1.0f - e, 1.0f + e);
    return copysignf(t, x);
}

// ============================================================
// Prep: decode adj + build ordered edge lists
// ============================================================
__global__ void k_prep(const unsigned char* __restrict__ adj_raw) {
    __shared__ float sadj[Nn * Nn];
    __shared__ int s_gt1, s_off4;
    const int tid = threadIdx.x;
    if (tid == 0) { s_gt1 = 0; s_off4 = 0; }
    __syncthreads();
    int f_gt1 = 0, f_off4 = 0;
    for (int t = tid; t < Nn * Nn; t += blockDim.x) {
        unsigned char c = adj_raw[t];
        if (c > 1) f_gt1 = 1;
        if (c == 1 && (t & 3) != 0) f_off4 = 1;
    }
    if (f_gt1)  atomicOr(&s_gt1, 1);
    if (f_off4) atomicOr(&s_off4, 1);
    __syncthreads();
    const int mode = s_gt1 ? 1 : (s_off4 ? 0 : 2);
    for (int e = tid; e < Nn * Nn; e += blockDim.x) {
        float v;
        if (mode == 1)      v = ((const float*)adj_raw)[e];
        else if (mode == 2) v = (float)(((const int*)adj_raw)[e]);
        else                v = (float)adj_raw[e];
        sadj[e] = v;
    }
    __syncthreads();
    if (tid < Nn) {
        const int i = tid; int c = 0;
        for (int j = 0; j < Nn; j++)
            if (sadj[j * Nn + i] != 0.0f) g_flist[i][c++] = j;
        g_fcnt[i] = c;
    } else if (tid < 2 * Nn) {
        const int i = tid - Nn; int c = 0;
        for (int j = Nn - 1; j >= 0; j--)
            if (sadj[i * Nn + j] != 0.0f) g_blist[i][c++] = j;
        g_bcnt[i] = c;
    }
}

// ============================================================
// Main scan: 256 blocks (128 fwd, 128 bwd), 8 samples each.
// Thread owns (dim kk, 4 samples); computes all 3 gates locally;
// ping-pong H -> ONE barrier per GRU step; first edge skips GEMV.
// ============================================================
__global__ void __launch_bounds__(TPB, 2) k_scan(
    const float* __restrict__ has, const float* __restrict__ z, const float* __restrict__ dz,
    const float* __restrict__ Wih_f, const float* __restrict__ Whh_f,
    const float* __restrict__ bih_f, const float* __restrict__ bhh_f,
    const float* __restrict__ Wih_b, const float* __restrict__ Whh_b,
    const float* __restrict__ bih_b, const float* __restrict__ bhh_b,
    const float* __restrict__ Wfp, const float* __restrict__ bfp,
    const float* __restrict__ Wbp, const float* __restrict__ bbp)
{
    extern __shared__ __align__(16) float sm[];
    const int dir = blockIdx.x >> 7;
    const int b0  = (blockIdx.x & 127) * GPB;
    const float* Wih = dir ? Wih_b : Wih_f;
    const float* Whh = dir ? Whh_b : Whh_f;
    const float* bih = dir ? bih_b : bih_f;
    const float* bhh = dir ? bhh_b : bhh_f;
    const float* Wp  = dir ? Wbp   : Wfp;
    const float* bp  = dir ? bbp   : bfp;
    float* grho = dir ? g_rho_b : g_rho_f;
    float* gic  = dir ? g_gi_b  : g_gi_f;

    const int  tid = threadIdx.x;
    const int  kk  = tid & 63;
    const int  sg  = tid >> 6;
    const bool act = kk < 60;

    // ---- stage weights/biases/has/zd(first node)
    for (int idx = tid; idx < 10800; idx += TPB) {
        const int r = idx / 60, c = idx - r * 60;
        sm[S_WHH + r * 68 + c] = Whh[idx];
    }
    for (int idx = tid; idx < 4800; idx += TPB)
        sm[S_WF + (idx / 80) * 84 + (idx % 80)] = Wp[idx];
    for (int idx = tid; idx < 60;  idx += TPB) sm[S_BF + idx]  = bp[idx];
    for (int idx = tid; idx < 180; idx += TPB) sm[S_BIH + idx] = bih[idx];
    for (int idx = tid; idx < 256; idx += TPB)
        sm[S_HAS + idx] = has[(size_t)(b0 + (idx >> 5)) * Nn + (idx & 31)];
    {
        const int i0 = dir ? (Nn - 1) : 0;
        for (int idx = tid; idx < 160; idx += TPB) {
            const int b = idx / 20, c = idx % 20;
            const size_t base = ((size_t)(b0 + b) * Nn + i0) * SE;
            sm[S_ZD + idx] = (c < SE) ? z[base + c] : dz[base + c - SE];
        }
    }
    const float bhh_r = act ? bhh[kk]        : 0.0f;
    const float bhh_z = act ? bhh[60 + kk]   : 0.0f;
    const float bhh_n = act ? bhh[120 + kk]  : 0.0f;
    __syncthreads();

    int rp = 0;                 // H read-buffer parity
    float h_old[4];

    // ================== node scan ==================
    for (int ii = 0; ii < Nn; ii++) {
        const int i = dir ? (Nn - 1 - ii) : ii;
        const int  cnt = dir ? g_bcnt[i] : g_fcnt[i];
        const int* lst = dir ? g_blist[i] : g_flist[i];

        #pragma unroll
        for (int m = 0; m < 4; m++) h_old[m] = 0.0f;

        if (cnt == 0) {
            if (act) {
                #pragma unroll
                for (int m = 0; m < 4; m++)
                    sm[S_H + rp * 512 + (sg * 4 + m) * 64 + kk] = 0.0f;
            }
            __syncthreads();
        } else {
            float giR[4], giZ[4], giN[4];
            if (act) {   // e=0 gi load (exposed once per node; prior bar guarantees gic)
                const float* gb = gic + ((size_t)lst[0] * Bsz + b0) * 180;
                #pragma unroll
                for (int m = 0; m < 4; m++) {
                    const float* gp = gb + (sg * 4 + m) * 180;
                    giR[m] = gp[kk]; giZ[m] = gp[60 + kk]; giN[m] = gp[120 + kk];
                }
            }
            for (int e = 0; e < cnt; e++) {
                const int j = lst[e];
                if (act) {
                    float aR[4] = {0,0,0,0}, aZ[4] = {0,0,0,0}, aN[4] = {0,0,0,0};
                    if (e > 0) {   // h==0 on first edge -> GEMV skipped entirely
                        const float* Hb = sm + S_H + rp * 512 + sg * 256;
                        #pragma unroll
                        for (int q = 0; q < 15; q++) {
                            const float4 wr = *(const float4*)(sm + S_WHH + kk * 68 + q * 4);
                            const float4 wz = *(const float4*)(sm + S_WHH + (60 + kk) * 68 + q * 4);
                            const float4 wn = *(const float4*)(sm + S_WHH + (120 + kk) * 68 + q * 4);
                            #pragma unroll
                            for (int m = 0; m < 4; m++) {
                                const float4 h = *(const float4*)(Hb + m * 64 + q * 4);
                                aR[m] += wr.x*h.x + wr.y*h.y + wr.z*h.z + wr.w*h.w;
                                aZ[m] += wz.x*h.x + wz.y*h.y + wz.z*h.z + wz.w*h.w;
                                aN[m] += wn.x*h.x + wn.y*h.y + wn.z*h.z + wn.w*h.w;
                            }
                        }
                    }
                    float nR[4], nZ[4], nN[4];
                    if (e + 1 < cnt) {    // prefetch next edge's gi
                        const float* gb = gic + ((size_t)lst[e + 1] * Bsz + b0) * 180;
                        #pragma unroll
                        for (int m = 0; m < 4; m++) {
                            const float* gp = gb + (sg * 4 + m) * 180;
                            nR[m] = gp[kk]; nZ[m] = gp[60 + kk]; nN[m] = gp[120 + kk];
                        }
                    }
                    #pragma unroll
                    for (int m = 0; m < 4; m++) {   // thread-local pointwise
                        const int b = sg * 4 + m;
                        const float r  = sigmf_(aR[m] + giR[m] + bhh_r);
                        const float u  = sigmf_(aZ[m] + giZ[m] + bhh_z);
                        const float nv = tanhsafe_(giN[m] + r * (aN[m] + bhh_n));
                        const float ho = h_old[m];
                        const float h2 = (1.0f - u) * nv + u * ho;
                        const float hn = ho + sm[S_HAS + b * 32 + j] * (h2 - ho);
                        h_old[m] = hn;
                        sm[S_H + (1 - rp) * 512 + b * 64 + kk] = hn;
                    }
                    if (e + 1 < cnt) {
                        #pragma unroll
                        for (int m = 0; m < 4; m++) { giR[m]=nR[m]; giZ[m]=nZ[m]; giN[m]=nN[m]; }
                    }
                }
                __syncthreads();   // ONE barrier per GRU step
                rp ^= 1;
            }
        }

        // ---- projection: thread handles its 4 samples at dim kk
        if (act) {
            #pragma unroll
            for (int m = 0; m < 4; m++) {
                const int b = sg * 4 + m;
                float acc = sm[S_BF + kk];
                const float4* wf4 = (const float4*)(sm + S_WF + kk * 84);
                const float4* hh  = (const float4*)(sm + S_H + rp * 512 + b * 64);
                const float4* zd4 = (const float4*)(sm + S_ZD + b * 20);
                #pragma unroll
                for (int q = 0; q < 15; q++) {
                    const float4 w = wf4[q], x = hh[q];
                    acc += w.x*x.x + w.y*x.y + w.z*x.z + w.w*x.w;
                }
                #pragma unroll
                for (int q = 0; q < 5; q++) {
                    const float4 w = wf4[15 + q], x = zd4[q];
                    acc += w.x*x.x + w.y*x.y + w.z*x.z + w.w*x.w;
                }
                if (dir == 0) acc = tanhsafe_(acc);
                sm[S_RHO + b * 64 + kk] = acc;
                grho[((size_t)i * Bsz + b0 + b) * 60 + kk] = acc;
            }
        }
        __syncthreads();   // sRHO visible; releases sZD for restage

        // ---- gi for node i (Wih via L2-hot LDG) + stage zd for next node
        if (act) {
            const int a = sg * 60 + kk;           // 0..119
            for (int rr = a; rr < 180; rr += 120) {
                float acc[GPB];
                const float bi = sm[S_BIH + rr];
                #pragma unroll
                for (int b = 0; b < GPB; b++) acc[b] = bi;
                const float4* wrow = (const float4*)(Wih + rr * 60);
                #pragma unroll
                for (int q = 0; q < 15; q++) {
                    const float4 w = __ldg(wrow + q);
                    #pragma unroll
                    for (int b = 0; b < GPB; b++) {
                        const float4 rv = *(const float4*)(sm + S_RHO + b * 64 + q * 4);
                        acc[b] += w.x*rv.x + w.y*rv.y + w.z*rv.z + w.w*rv.w;
                    }
                }
                #pragma unroll
                for (int b = 0; b < GPB; b++)
                    gic[((size_t)i * Bsz + b0 + b) * 180 + rr] = acc[b];
            }
        }
        if (ii + 1 < Nn) {
            const int i2 = dir ? (Nn - 2 - ii) : (ii + 1);
            for (int idx = tid; idx < 160; idx += TPB) {
                const int b = idx / 20, c = idx % 20;
                const size_t base = ((size_t)(b0 + b) * Nn + i2) * SE;
                sm[S_ZD + idx] = (c < SE) ? z[base + c] : dz[base + c - SE];
            }
        }
        __syncthreads();   // gic(i) visible before any later edge reads it
    }

    // ================== alpha scan ==================
    #pragma unroll
    for (int m = 0; m < 4; m++) h_old[m] = 0.0f;
    const int steps = dir ? IIN : OOUT;
    for (int s = 0; s < steps; s++) {
        const int i = dir ? (IIN - 1 - s) : (Nn - OOUT + s);
        if (act) {
            float giR[4], giZ[4], giN[4];
            const float* gb = gic + ((size_t)i * Bsz + b0) * 180;
            #pragma unroll
            for (int m = 0; m < 4; m++) {
                const float* gp = gb + (sg * 4 + m) * 180;
                giR[m] = gp[kk]; giZ[m] = gp[60 + kk]; giN[m] = gp[120 + kk];
            }
            float aR[4] = {0,0,0,0}, aZ[4] = {0,0,0,0}, aN[4] = {0,0,0,0};
            if (s > 0) {
                const float* Hb = sm + S_H + rp * 512 + sg * 256;
                #pragma unroll
                for (int q = 0; q < 15; q++) {
                    const float4 wr = *(const float4*)(sm + S_WHH + kk * 68 + q * 4);
                    const float4 wz = *(const float4*)(sm + S_WHH + (60 + kk) * 68 + q * 4);
                    const float4 wn = *(const float4*)(sm + S_WHH + (120 + kk) * 68 + q * 4);
                    #pragma unroll
                    for (int m = 0; m < 4; m++) {
                        const float4 h = *(const float4*)(Hb + m * 64 + q * 4);
                        aR[m] += wr.x*h.x + wr.y*h.y + wr.z*h.z + wr.w*h.w;
                        aZ[m] += wz.x*h.x + wz.y*h.y + wz.z*h.z + wz.w*h.w;
                        aN[m] += wn.x*h.x + wn.y*h.y + wn.z*h.z + wn.w*h.w;
                    }
                }
            }
            #pragma unroll
            for (int m = 0; m < 4; m++) {
                const int b = sg * 4 + m;
                const float r  = sigmf_(aR[m] + giR[m] + bhh_r);
                const float u  = sigmf_(aZ[m] + giZ[m] + bhh_z);
                const float nv = tanhsafe_(giN[m] + r * (aN[m] + bhh_n));
                const float ho = h_old[m];
                const float h2 = (1.0f - u) * nv + u * ho;
                const float hn = ho + sm[S_HAS + b * 32 + i] * (h2 - ho);
                h_old[m] = hn;
                sm[S_H + (1 - rp) * 512 + b * 64 + kk] = hn;
            }
        }
        __syncthreads();
        rp ^= 1;
    }
    if (act) {
        float* ga = dir ? g_ab : g_af;
        #pragma unroll
        for (int m = 0; m < 4; m++)
            ga[(size_t)(b0 + sg * 4 + m) * 60 + kk] = h_old[m];
    }
}

// ============================================================
// Heads: blocks [0,128) role_prob; [128,144) instr_prob + value
// out: [0,5120) instr | [5120,234496) roles | [234496,235520) value
// ============================================================
__global__ void k_heads(const float* __restrict__ has,
                        const float* __restrict__ Wu, const float* __restrict__ bu,
                        const float* __restrict__ Wa, const float* __restrict__ ba,
                        const float* __restrict__ Wc, const float* __restrict__ bc,
                        float* __restrict__ out)
{
    const int tid = threadIdx.x;
    if (blockIdx.x < 128) {
        __shared__ __align__(16) float sWu[7 * 120];
        __shared__ float sbu[7];
        for (int idx = tid; idx < 840; idx += blockDim.x) sWu[idx] = Wu[idx];
        if (tid < 7) sbu[tid] = bu[tid];
        __syncthreads();

        const int t = blockIdx.x * 256 + tid;
        const int b = t >> 5;
        const int n = t & 31;

        float acc[7];
        #pragma unroll
        for (int r = 0; r < 7; r++) acc[r] = sbu[r];

        const float4* rf = (const float4*)(g_rho_f + ((size_t)n * Bsz + b) * 60);
        const float4* rb = (const float4*)(g_rho_b + ((size_t)n * Bsz + b) * 60);
        #pragma unroll
        for (int q = 0; q < 15; q++) {
            const float4 f = rf[q];
            #pragma unroll
            for (int r = 0; r < 7; r++) {
                const float4 w = *(const float4*)(sWu + r * 120 + q * 4);
                acc[r] += w.x*f.x + w.y*f.y + w.z*f.z + w.w*f.w;
            }
        }
        #pragma unroll
        for (int q = 0; q < 15; q++) {
            const float4 f = rb[q];
            #pragma unroll
            for (int r = 0; r < 7; r++) {
                const float4 w = *(const float4*)(sWu + r * 120 + 60 + q * 4);
                acc[r] += w.x*f.x + w.y*f.y + w.z*f.z + w.w*f.w;
            }
        }
        const float m = has[b * Nn + n];
        float l[7], mx = -1e30f;
        #pragma unroll
        for (int r = 0; r < 7; r++) { l[r] = (m != 0.0f) ? acc[r] : -60.0f; mx = fmaxf(mx, l[r]); }
        float s = 0.0f;
        #pragma unroll
        for (int r = 0; r < 7; r++) { l[r] = __expf(l[r] - mx); s += l[r]; }
        const float inv = __fdividef(1.0f, s);
        float* ro = out + 5120;
        #pragma unroll
        for (int r = 0; r < 7; r++) ro[((size_t)b * 7 + r) * 32 + n] = l[r] * inv;
    } else {
        __shared__ __align__(16) float sWa[5 * 120];
        __shared__ __align__(16) float sWc[120];
        __shared__ float sba[5];
        __shared__ float sbc;
        for (int idx = tid; idx < 600; idx += blockDim.x) sWa[idx] = Wa[idx];
        for (int idx = tid; idx < 120; idx += blockDim.x) sWc[idx] = Wc[idx];
        if (tid < 5) sba[tid] = ba[tid];
        if (tid == 0) sbc = bc[0];
        __syncthreads();

        const int t    = (blockIdx.x - 128) * 256 + tid;
        const int b    = t >> 2;
        const int lane = t & 3;

        float acc[6];
        #pragma unroll
        for (int a = 0; a < 6; a++) acc[a] = 0.0f;

        const float4* af = (const float4*)(g_af + (size_t)b * 60);
        const float4* ab = (const float4*)(g_ab + (size_t)b * 60);
        for (int q = lane; q < 30; q += 4) {
            const float4 f = (q < 15) ? af[q] : ab[q - 15];
            #pragma unroll
            for (int a = 0; a < 5; a++) {
                const float4 w = *(const float4*)(sWa + a * 120 + q * 4);
                acc[a] += w.x*f.x + w.y*f.y + w.z*f.z + w.w*f.w;
            }
            const float4 wc = *(const float4*)(sWc + q * 4);
            acc[5] += wc.x*f.x + wc.y*f.y + wc.z*f.z + wc.w*f.w;
        }
        #pragma unroll
        for (int off = 1; off < 4; off <<= 1) {
            #pragma unroll
            for (int a = 0; a < 6; a++)
                acc[a] += __shfl_xor_sync(0xffffffffu, acc[a], off);
        }
        if (lane == 0) {
            float l[5], mx = -1e30f;
            #pragma unroll
            for (int a = 0; a < 5; a++) { l[a] = acc[a] + sba[a]; mx = fmaxf(mx, l[a]); }
            float s = 0.0f;
            #pragma unroll
            for (int a = 0; a < 5; a++) { l[a] = __expf(l[a] - mx); s += l[a]; }
            const float inv = __fdividef(1.0f, s);
            #pragma unroll
            for (int a = 0; a < 5; a++) out[b * 5 + a] = l[a] * inv;
            out[5120 + Bsz * 7 * Nn + b] = acc[5] + sbc;   // value @ 234496
        }
    }
}

// ============================================================
extern "C" void kernel_launch(void* const* d_in, const int* in_sizes, int n_in,
                              void* d_out, int out_size)
{
    const float* has   = (const float*)d_in[0];
    const float* z     = (const float*)d_in[1];
    const float* dz    = (const float*)d_in[2];
    const unsigned char* adj = (const unsigned char*)d_in[3];
    const float* Wih_f = (const float*)d_in[4];
    const float* Whh_f = (const float*)d_in[5];
    const float* bih_f = (const float*)d_in[6];
    const float* bhh_f = (const float*)d_in[7];
    const float* Wih_b = (const float*)d_in[8];
    const float* Whh_b = (const float*)d_in[9];
    const float* bih_b = (const float*)d_in[10];
    const float* bhh_b = (const float*)d_in[11];
    const float* Wf    = (const float*)d_in[12];
    const float* bf    = (const float*)d_in[13];
    const float* Wb    = (const float*)d_in[14];
    const float* bb    = (const float*)d_in[15];
    const float* Wa    = (const float*)d_in[16];
    const float* ba    = (const float*)d_in[17];
    const float* Wc    = (const float*)d_in[18];
    const float* bc    = (const float*)d_in[19];
    const float* Wu    = (const float*)d_in[20];
    const float* bu    = (const float*)d_in[21];
    float* out = (float*)d_out;

    const size_t smem = SMEM_FLOATS * sizeof(float);   // ~76 KB -> 2 blocks/SM
    cudaFuncSetAttribute(k_scan, cudaFuncAttributeMaxDynamicSharedMemorySize, (int)smem);

    k_prep<<<1, 256>>>(adj);
    k_scan<<<256, TPB, smem>>>(has, z, dz,
                               Wih_f, Whh_f, bih_f, bhh_f,
                               Wih_b, Whh_b, bih_b, bhh_b,
                               Wf, bf, Wb, bb);
    k_heads<<<144, 256>>>(has, Wu, bu, Wa, ba, Wc, bc, out);
}

// round 8
// speedup vs baseline: 1.2436x; 1.0201x over previous
#include <cuda_runtime.h>
#include <math.h>

#define Bsz   1024
#define Nn    32
#define SE    10
#define OOUT  5
#define IIN   6
#define GPB   16     // samples per block
#define TPB   128    // 4 warps x 4 samples; lane<30 owns dims {l, l+30}

// ---- shared memory layout (float offsets; all 16B-aligned) ----
#define S_WHH 0        // 180 rows x 68 = 12240
#define S_WF  12240    // 60 rows x 84 = 5040
#define S_BIH 17280    // 180
#define S_BF  17460    // 60
#define S_HAS 17520    // 16*32 = 512
#define S_ZD  18032    // 16*20 = 320
#define S_H   18352    // 4 warps x 2 bufs x 4 samples x 64 = 2048
#define S_RHO 20400    // 16*64 = 1024
#define SMEM_FLOATS 21424   // ~86 KB -> 1 block/SM

// ---- device scratch ----
__device__ int   g_fcnt[Nn];
__device__ int   g_flist[Nn][Nn];
__device__ int   g_bcnt[Nn];
__device__ int   g_blist[Nn][Nn];
__device__ float g_rho_f[Nn * Bsz * 60];
__device__ float g_rho_b[Nn * Bsz * 60];
__device__ float g_af[Bsz * 60];
__device__ float g_ab[Bsz * 60];
__device__ float g_gi_f[Nn * Bsz * 180];   // gi cache incl. bih: [node][b][row]
__device__ float g_gi_b[Nn * Bsz * 180];

__device__ __forceinline__ void fma2(unsigned long long& a,
                                     unsigned long long b, unsigned long long c) {
    asm("fma.rn.f32x2 %0,%1,%2,%0;" : "+l"(a) : "l"(b), "l"(c));
}
__device__ __forceinline__ float red2(unsigned long long v) {
    float x, y;
    asm("mov.b64 {%0,%1},%2;" : "=f"(x), "=f"(y) : "l"(v));
    return x + y;
}
__device__ __forceinline__ unsigned long long seed2(float x) {
    return (unsigned long long)__float_as_uint(x);   // (x, +0.0f)
}
__device__ __forceinline__ float sigmf_(float x) {
    return __fdividef(1.0f, 1.0f + __expf(-x));
}
__device__ __forceinline__ float tanhsafe_(float x) {
    float a = fabsf(x);
    float e = __expf(-2.0f * a);
    float t = __fdividef(1.0f - e, 1.0f + e);
    return copysignf(t, x);
}

// ============================================================
// Prep: decode adj + build ordered edge lists
// ============================================================
__global__ void k_prep(const unsigned char* __restrict__ adj_raw) {
    __shared__ float sadj[Nn * Nn];
    __shared__ int s_gt1, s_off4;
    const int tid = threadIdx.x;
    if (tid == 0) { s_gt1 = 0; s_off4 = 0; }
    __syncthreads();
    int f_gt1 = 0, f_off4 = 0;
    for (int t = tid; t < Nn * Nn; t += blockDim.x) {
        unsigned char c = adj_raw[t];
        if (c > 1) f_gt1 = 1;
        if (c == 1 && (t & 3) != 0) f_off4 = 1;
    }
    if (f_gt1)  atomicOr(&s_gt1, 1);
    if (f_off4) atomicOr(&s_off4, 1);
    __syncthreads();
    const int mode = s_gt1 ? 1 : (s_off4 ? 0 : 2);
    for (int e = tid; e < Nn * Nn; e += blockDim.x) {
        float v;
        if (mode == 1)      v = ((const float*)adj_raw)[e];
        else if (mode == 2) v = (float)(((const int*)adj_raw)[e]);
        else                v = (float)adj_raw[e];
        sadj[e] = v;
    }
    __syncthreads();
    if (tid < Nn) {
        const int i = tid; int c = 0;
        for (int j = 0; j < Nn; j++)
            if (sadj[j * Nn + i] != 0.0f) g_flist[i][c++] = j;
        g_fcnt[i] = c;
    } else if (tid < 2 * Nn) {
        const int i = tid - Nn; int c = 0;
        for (int j = Nn - 1; j >= 0; j--)
            if (sadj[i * Nn + j] != 0.0f) g_blist[i][c++] = j;
        g_bcnt[i] = c;
    }
}

// ============================================================
// Main scan: 128 blocks (64 fwd, 64 bwd), 16 samples each.
// Warp owns 4 samples end-to-end: NO block barriers in the scan.
// All GEMVs in packed f32x2.
// ============================================================
__global__ void __launch_bounds__(TPB, 1) k_scan(
    const float* __restrict__ has, const float* __restrict__ z, const float* __restrict__ dz,
    const float* __restrict__ Wih_f, const float* __restrict__ Whh_f,
    const float* __restrict__ bih_f, const float* __restrict__ bhh_f,
    const float* __restrict__ Wih_b, const float* __restrict__ Whh_b,
    const float* __restrict__ bih_b, const float* __restrict__ bhh_b,
    const float* __restrict__ Wfp, const float* __restrict__ bfp,
    const float* __restrict__ Wbp, const float* __restrict__ bbp)
{
    extern __shared__ __align__(16) float sm[];
    const int dir = blockIdx.x >> 6;
    const int b0  = (blockIdx.x & 63) * GPB;
    const float* Wih = dir ? Wih_b : Wih_f;
    const float* Whh = dir ? Whh_b : Whh_f;
    const float* bih = dir ? bih_b : bih_f;
    const float* bhh = dir ? bhh_b : bhh_f;
    const float* Wp  = dir ? Wbp   : Wfp;
    const float* bp  = dir ? bbp   : bfp;
    float* grho = dir ? g_rho_b : g_rho_f;
    float* gic  = dir ? g_gi_b  : g_gi_f;

    const int  tid  = threadIdx.x;
    const int  warp = tid >> 5;
    const int  lane = tid & 31;
    const int  sb   = warp * 4;          // warp's sample base within block
    const bool act  = lane < 30;
    const int  d0   = lane, d1 = lane + 30;

    // ---- block-wide staging (the ONLY __syncthreads)
    for (int idx = tid; idx < 10800; idx += TPB) {
        const int r = idx / 60, c = idx - r * 60;
        sm[S_WHH + r * 68 + c] = Whh[idx];
    }
    for (int idx = tid; idx < 4800; idx += TPB)
        sm[S_WF + (idx / 80) * 84 + (idx % 80)] = Wp[idx];
    for (int idx = tid; idx < 180; idx += TPB) sm[S_BIH + idx] = bih[idx];
    for (int idx = tid; idx < 60;  idx += TPB) sm[S_BF + idx]  = bp[idx];
    for (int idx = tid; idx < GPB * Nn; idx += TPB)
        sm[S_HAS + idx] = has[(size_t)(b0 + (idx >> 5)) * Nn + (idx & 31)];
    __syncthreads();

    // per-lane constants (6 rows: rP={r,d0},{r,d1}, z, n likewise)
    int rows[6];
    rows[0] = d0;        rows[1] = d1;
    rows[2] = 60 + d0;   rows[3] = 60 + d1;
    rows[4] = 120 + d0;  rows[5] = 120 + d1;
    float bhhv[6];
    #pragma unroll
    for (int r = 0; r < 6; r++) bhhv[r] = act ? bhh[rows[r]] : 0.0f;

    float* sHw = sm + S_H + warp * 512;  // [buf 2][sample 4][64]

    int rp = 0;
    float h_old[2][4];
    float gi[6][4], gin[6][4], a6[6][4];

    // ================== node scan ==================
    for (int ii = 0; ii < Nn; ii++) {
        const int i = dir ? (Nn - 1 - ii) : ii;

        // stage this node's z/dz for the warp's samples (proj consumes later)
        for (int idx = lane; idx < 80; idx += 32) {
            const int m = idx / 20, c = idx % 20;
            const size_t base = ((size_t)(b0 + sb + m) * Nn + i) * SE;
            sm[S_ZD + (sb + m) * 20 + c] = (c < SE) ? z[base + c] : dz[base + c - SE];
        }

        const int  cnt = dir ? g_bcnt[i] : g_fcnt[i];
        const int* lst = dir ? g_blist[i] : g_flist[i];

        #pragma unroll
        for (int t = 0; t < 2; t++)
            #pragma unroll
            for (int m = 0; m < 4; m++) h_old[t][m] = 0.0f;

        if (cnt == 0) {
            if (act) {
                #pragma unroll
                for (int m = 0; m < 4; m++) {
                    sHw[rp * 256 + m * 64 + d0] = 0.0f;
                    sHw[rp * 256 + m * 64 + d1] = 0.0f;
                }
            }
            __syncwarp();
        } else {
            if (act) {   // e=0 gi load (same-lane rows; gic written by this lane)
                const float* gb = gic + ((size_t)lst[0] * Bsz + b0 + sb) * 180;
                #pragma unroll
                for (int m = 0; m < 4; m++)
                    #pragma unroll
                    for (int r = 0; r < 6; r++) gi[r][m] = gb[m * 180 + rows[r]];
            }
            for (int e = 0; e < cnt; e++) {
                const int j = lst[e];
                if (act) {
                    if (e > 0) {
                        unsigned long long acc[6][4];
                        #pragma unroll
                        for (int r = 0; r < 6; r++)
                            #pragma unroll
                            for (int m = 0; m < 4; m++) acc[r][m] = 0ULL;
                        #pragma unroll
                        for (int q = 0; q < 15; q++) {
                            ulonglong2 w[6];
                            #pragma unroll
                            for (int r = 0; r < 6; r++)
                                w[r] = *(const ulonglong2*)(sm + S_WHH + rows[r] * 68 + q * 4);
                            #pragma unroll
                            for (int m = 0; m < 4; m++) {
                                const ulonglong2 h =
                                    *(const ulonglong2*)(sHw + rp * 256 + m * 64 + q * 4);
                                #pragma unroll
                                for (int r = 0; r < 6; r++) {
                                    fma2(acc[r][m], w[r].x, h.x);
                                    fma2(acc[r][m], w[r].y, h.y);
                                }
                            }
                        }
                        #pragma unroll
                        for (int r = 0; r < 6; r++)
                            #pragma unroll
                            for (int m = 0; m < 4; m++) a6[r][m] = red2(acc[r][m]);
                    } else {
                        #pragma unroll
                        for (int r = 0; r < 6; r++)
                            #pragma unroll
                            for (int m = 0; m < 4; m++) a6[r][m] = 0.0f;
                    }
                    if (e + 1 < cnt) {   // prefetch next gi
                        const float* gb = gic + ((size_t)lst[e + 1] * Bsz + b0 + sb) * 180;
                        #pragma unroll
                        for (int m = 0; m < 4; m++)
                            #pragma unroll
                            for (int r = 0; r < 6; r++) gin[r][m] = gb[m * 180 + rows[r]];
                    }
                    #pragma unroll
                    for (int m = 0; m < 4; m++) {
                        const float mask = sm[S_HAS + (sb + m) * 32 + j];
                        #pragma unroll
                        for (int t = 0; t < 2; t++) {
                            const float r  = sigmf_(a6[t][m] + gi[t][m] + bhhv[t]);
                            const float u  = sigmf_(a6[2 + t][m] + gi[2 + t][m] + bhhv[2 + t]);
                            const float nv = tanhsafe_(gi[4 + t][m]
                                              + r * (a6[4 + t][m] + bhhv[4 + t]));
                            const float ho = h_old[t][m];
                            const float h2 = (1.0f - u) * nv + u * ho;
                            const float hn = ho + mask * (h2 - ho);
                            h_old[t][m] = hn;
                            sHw[(1 - rp) * 256 + m * 64 + (t ? d1 : d0)] = hn;
                        }
                    }
                    if (e + 1 < cnt) {
                        #pragma unroll
                        for (int r = 0; r < 6; r++)
                            #pragma unroll
                            for (int m = 0; m < 4; m++) gi[r][m] = gin[r][m];
                    }
                }
                __syncwarp();
                rp ^= 1;
            }
        }

        // ---- projection (reads sH[rp] + zd; writes sRHO + g_rho)
        if (act) {
            #pragma unroll
            for (int m = 0; m < 4; m++) {
                #pragma unroll
                for (int t = 0; t < 2; t++) {
                    const int d = t ? d1 : d0;
                    unsigned long long acc = seed2(sm[S_BF + d]);
                    const ulonglong2* Wr = (const ulonglong2*)(sm + S_WF + d * 84);
                    const ulonglong2* Hh = (const ulonglong2*)(sHw + rp * 256 + m * 64);
                    #pragma unroll
                    for (int q = 0; q < 15; q++) {
                        const ulonglong2 w = Wr[q], h = Hh[q];
                        fma2(acc, w.x, h.x); fma2(acc, w.y, h.y);
                    }
                    const ulonglong2* Zd = (const ulonglong2*)(sm + S_ZD + (sb + m) * 20);
                    #pragma unroll
                    for (int q = 0; q < 5; q++) {
                        const ulonglong2 w = Wr[15 + q], x = Zd[q];
                        fma2(acc, w.x, x.x); fma2(acc, w.y, x.y);
                    }
                    float val = red2(acc);
                    if (dir == 0) val = tanhsafe_(val);
                    sm[S_RHO + (sb + m) * 64 + d] = val;
                    grho[((size_t)i * Bsz + b0 + sb + m) * 60 + d] = val;
                }
            }
        }
        __syncwarp();   // sRHO visible within warp

        // ---- gi for node i: rows {lane+30t}, 4 samples (Wih via LDG, L2-hot)
        if (act) {
            unsigned long long acc[6][4];
            #pragma unroll
            for (int r = 0; r < 6; r++) {
                const float bi = sm[S_BIH + lane + 30 * r];
                #pragma unroll
                for (int m = 0; m < 4; m++) acc[r][m] = seed2(bi);
            }
            #pragma unroll
            for (int q = 0; q < 15; q++) {
                ulonglong2 w[6];
                #pragma unroll
                for (int r = 0; r < 6; r++)
                    w[r] = *(const ulonglong2*)(Wih + (lane + 30 * r) * 60 + q * 4);
                #pragma unroll
                for (int m = 0; m < 4; m++) {
                    const ulonglong2 rv =
                        *(const ulonglong2*)(sm + S_RHO + (sb + m) * 64 + q * 4);
                    #pragma unroll
                    for (int r = 0; r < 6; r++) {
                        fma2(acc[r][m], w[r].x, rv.x);
                        fma2(acc[r][m], w[r].y, rv.y);
                    }
                }
            }
            #pragma unroll
            for (int r = 0; r < 6; r++)
                #pragma unroll
                for (int m = 0; m < 4; m++)
                    gic[((size_t)i * Bsz + b0 + sb + m) * 180 + lane + 30 * r]
                        = red2(acc[r][m]);
        }
        __syncwarp();   // zd restage (next node) must not pass proj reads
    }

    // ================== alpha scan ==================
    #pragma unroll
    for (int t = 0; t < 2; t++)
        #pragma unroll
        for (int m = 0; m < 4; m++) h_old[t][m] = 0.0f;
    const int steps = dir ? IIN : OOUT;
    for (int s = 0; s < steps; s++) {
        const int i = dir ? (IIN - 1 - s) : (Nn - OOUT + s);
        if (act) {
            const float* gb = gic + ((size_t)i * Bsz + b0 + sb) * 180;
            #pragma unroll
            for (int m = 0; m < 4; m++)
                #pragma unroll
                for (int r = 0; r < 6; r++) gi[r][m] = gb[m * 180 + rows[r]];
            if (s > 0) {
                unsigned long long acc[6][4];
                #pragma unroll
                for (int r = 0; r < 6; r++)
                    #pragma unroll
                    for (int m = 0; m < 4; m++) acc[r][m] = 0ULL;
                #pragma unroll
                for (int q = 0; q < 15; q++) {
                    ulonglong2 w[6];
                    #pragma unroll
                    for (int r = 0; r < 6; r++)
                        w[r] = *(const ulonglong2*)(sm + S_WHH + rows[r] * 68 + q * 4);
                    #pragma unroll
                    for (int m = 0; m < 4; m++) {
                        const ulonglong2 h =
                            *(const ulonglong2*)(sHw + rp * 256 + m * 64 + q * 4);
                        #pragma unroll
                        for (int r = 0; r < 6; r++) {
                            fma2(acc[r][m], w[r].x, h.x);
                            fma2(acc[r][m], w[r].y, h.y);
                        }
                    }
                }
                #pragma unroll
                for (int r = 0; r < 6; r++)
                    #pragma unroll
                    for (int m = 0; m < 4; m++) a6[r][m] = red2(acc[r][m]);
            } else {
                #pragma unroll
                for (int r = 0; r < 6; r++)
                    #pragma unroll
                    for (int m = 0; m < 4; m++) a6[r][m] = 0.0f;
            }
            #pragma unroll
            for (int m = 0; m < 4; m++) {
                const float mask = sm[S_HAS + (sb + m) * 32 + i];
                #pragma unroll
                for (int t = 0; t < 2; t++) {
                    const float r  = sigmf_(a6[t][m] + gi[t][m] + bhhv[t]);
                    const float u  = sigmf_(a6[2 + t][m] + gi[2 + t][m] + bhhv[2 + t]);
                    const float nv = tanhsafe_(gi[4 + t][m]
                                      + r * (a6[4 + t][m] + bhhv[4 + t]));
                    const float ho = h_old[t][m];
                    const float h2 = (1.0f - u) * nv + u * ho;
                    const float hn = ho + mask * (h2 - ho);
                    h_old[t][m] = hn;
                    sHw[(1 - rp) * 256 + m * 64 + (t ? d1 : d0)] = hn;
                }
            }
        }
        __syncwarp();
        rp ^= 1;
    }
    if (act) {
        float* ga = dir ? g_ab : g_af;
        #pragma unroll
        for (int m = 0; m < 4; m++) {
            ga[(size_t)(b0 + sb + m) * 60 + d0] = h_old[0][m];
            ga[(size_t)(b0 + sb + m) * 60 + d1] = h_old[1][m];
        }
    }
}

// ============================================================
// Heads: blocks [0,128) role_prob; [128,144) instr_prob + value
// out: [0,5120) instr | [5120,234496) roles | [234496,235520) value
// ============================================================
__global__ void k_heads(const float* __restrict__ has,
                        const float* __restrict__ Wu, const float* __restrict__ bu,
                        const float* __restrict__ Wa, const float* __restrict__ ba,
                        const float* __restrict__ Wc, const float* __restrict__ bc,
                        float* __restrict__ out)
{
    const int tid = threadIdx.x;
    if (blockIdx.x < 128) {
        __shared__ __align__(16) float sWu[7 * 120];
        __shared__ float sbu[7];
        for (int idx = tid; idx < 840; idx += blockDim.x) sWu[idx] = Wu[idx];
        if (tid < 7) sbu[tid] = bu[tid];
        __syncthreads();

        const int t = blockIdx.x * 256 + tid;
        const int b = t >> 5;
        const int n = t & 31;

        float acc[7];
        #pragma unroll
        for (int r = 0; r < 7; r++) acc[r] = sbu[r];

        const float4* rf = (const float4*)(g_rho_f + ((size_t)n * Bsz + b) * 60);
        const float4* rb = (const float4*)(g_rho_b + ((size_t)n * Bsz + b) * 60);
        #pragma unroll
        for (int q = 0; q < 15; q++) {
            const float4 f = rf[q];
            #pragma unroll
            for (int r = 0; r < 7; r++) {
                const float4 w = *(const float4*)(sWu + r * 120 + q * 4);
                acc[r] += w.x*f.x + w.y*f.y + w.z*f.z + w.w*f.w;
            }
        }
        #pragma unroll
        for (int q = 0; q < 15; q++) {
            const float4 f = rb[q];
            #pragma unroll
            for (int r = 0; r < 7; r++) {
                const float4 w = *(const float4*)(sWu + r * 120 + 60 + q * 4);
                acc[r] += w.x*f.x + w.y*f.y + w.z*f.z + w.w*f.w;
            }
        }
        const float m = has[b * Nn + n];
        float l[7], mx = -1e30f;
        #pragma unroll
        for (int r = 0; r < 7; r++) { l[r] = (m != 0.0f) ? acc[r] : -60.0f; mx = fmaxf(mx, l[r]); }
        float s = 0.0f;
        #pragma unroll
        for (int r = 0; r < 7; r++) { l[r] = __expf(l[r] - mx); s += l[r]; }
        const float inv = __fdividef(1.0f, s);
        float* ro = out + 5120;
        #pragma unroll
        for (int r = 0; r < 7; r++) ro[((size_t)b * 7 + r) * 32 + n] = l[r] * inv;
    } else {
        __shared__ __align__(16) float sWa[5 * 120];
        __shared__ __align__(16) float sWc[120];
        __shared__ float sba[5];
        __shared__ float sbc;
        for (int idx = tid; idx < 600; idx += blockDim.x) sWa[idx] = Wa[idx];
        for (int idx = tid; idx < 120; idx += blockDim.x) sWc[idx] = Wc[idx];
        if (tid < 5) sba[tid] = ba[tid];
        if (tid == 0) sbc = bc[0];
        __syncthreads();

        const int t    = (blockIdx.x - 128) * 256 + tid;
        const int b    = t >> 2;
        const int lane = t & 3;

        float acc[6];
        #pragma unroll
        for (int a = 0; a < 6; a++) acc[a] = 0.0f;

        const float4* af = (const float4*)(g_af + (size_t)b * 60);
        const float4* ab = (const float4*)(g_ab + (size_t)b * 60);
        for (int q = lane; q < 30; q += 4) {
            const float4 f = (q < 15) ? af[q] : ab[q - 15];
            #pragma unroll
            for (int a = 0; a < 5; a++) {
                const float4 w = *(const float4*)(sWa + a * 120 + q * 4);
                acc[a] += w.x*f.x + w.y*f.y + w.z*f.z + w.w*f.w;
            }
            const float4 wc = *(const float4*)(sWc + q * 4);
            acc[5] += wc.x*f.x + wc.y*f.y + wc.z*f.z + wc.w*f.w;
        }
        #pragma unroll
        for (int off = 1; off < 4; off <<= 1) {
            #pragma unroll
            for (int a = 0; a < 6; a++)
                acc[a] += __shfl_xor_sync(0xffffffffu, acc[a], off);
        }
        if (lane == 0) {
            float l[5], mx = -1e30f;
            #pragma unroll
            for (int a = 0; a < 5; a++) { l[a] = acc[a] + sba[a]; mx = fmaxf(mx, l[a]); }
            float s = 0.0f;
            #pragma unroll
            for (int a = 0; a < 5; a++) { l[a] = __expf(l[a] - mx); s += l[a]; }
            const float inv = __fdividef(1.0f, s);
            #pragma unroll
            for (int a = 0; a < 5; a++) out[b * 5 + a] = l[a] * inv;
            out[5120 + Bsz * 7 * Nn + b] = acc[5] + sbc;   // value @ 234496
        }
    }
}

// ============================================================
extern "C" void kernel_launch(void* const* d_in, const int* in_sizes, int n_in,
                              void* d_out, int out_size)
{
    const float* has   = (const float*)d_in[0];
    const float* z     = (const float*)d_in[1];
    const float* dz    = (const float*)d_in[2];
    const unsigned char* adj = (const unsigned char*)d_in[3];
    const float* Wih_f = (const float*)d_in[4];
    const float* Whh_f = (const float*)d_in[5];
    const float* bih_f = (const float*)d_in[6];
    const float* bhh_f = (const float*)d_in[7];
    const float* Wih_b = (const float*)d_in[8];
    const float* Whh_b = (const float*)d_in[9];
    const float* bih_b = (const float*)d_in[10];
    const float* bhh_b = (const float*)d_in[11];
    const float* Wf    = (const float*)d_in[12];
    const float* bf    = (const float*)d_in[13];
    const float* Wb    = (const float*)d_in[14];
    const float* bb    = (const float*)d_in[15];
    const float* Wa    = (const float*)d_in[16];
    const float* ba    = (const float*)d_in[17];
    const float* Wc    = (const float*)d_in[18];
    const float* bc    = (const float*)d_in[19];
    const float* Wu    = (const float*)d_in[20];
    const float* bu    = (const float*)d_in[21];
    float* out = (float*)d_out;

    const size_t smem = SMEM_FLOATS * sizeof(float);   // ~86 KB -> 1 block/SM
    cudaFuncSetAttribute(k_scan, cudaFuncAttributeMaxDynamicSharedMemorySize, (int)smem);

    k_prep<<<1, 256>>>(adj);
    k_scan<<<128, TPB, smem>>>(has, z, dz,
                               Wih_f, Whh_f, bih_f, bhh_f,
                               Wih_b, Whh_b, bih_b, bhh_b,
                               Wf, bf, Wb, bb);
    k_heads<<<144, 256>>>(has, Wu, bu, Wa, ba, Wc, bc, out);
}

// round 9
// speedup vs baseline: 1.7013x; 1.3681x over previous
#include <cuda_runtime.h>
#include <math.h>

#define Bsz   1024
#define Nn    32
#define SE    10
#define OOUT  5
#define IIN   6
#define GPB   16     // samples per block
#define TPB   256    // 8 warps = 4 pairs; pair owns 4 samples; warp owns 30 dims

// ---- shared memory layout (float offsets; all 16B-aligned) ----
#define S_WHH 0        // 180 x 68 = 12240
#define S_WIH 12240    // 180 x 68 = 12240
#define S_WF  24480    // 60 x 84 = 5040
#define S_BIH 29520    // 180
#define S_BF  29700    // 60
#define S_HAS 29760    // 16*32 = 512
#define S_ZD  30272    // 16*20 = 320
#define S_H   30592    // 4 pairs x 2 bufs x 4 samples x 64 = 2048
#define S_RHO 32640    // 16*64 = 1024
#define SMEM_FLOATS 33664   // ~132 KB -> 1 block/SM

// ---- device scratch ----
__device__ int   g_fcnt[Nn];
__device__ int   g_flist[Nn][Nn];
__device__ int   g_bcnt[Nn];
__device__ int   g_blist[Nn][Nn];
__device__ float g_rho_f[Nn * Bsz * 60];
__device__ float g_rho_b[Nn * Bsz * 60];
__device__ float g_af[Bsz * 60];
__device__ float g_ab[Bsz * 60];
__device__ float g_gi_f[Nn * Bsz * 180];   // gi cache incl. bih: [node][b][row]
__device__ float g_gi_b[Nn * Bsz * 180];

__device__ __forceinline__ void fma2(unsigned long long& a,
                                     unsigned long long b, unsigned long long c) {
    asm("fma.rn.f32x2 %0,%1,%2,%0;" : "+l"(a) : "l"(b), "l"(c));
}
__device__ __forceinline__ float red2(unsigned long long v) {
    float x, y;
    asm("mov.b64 {%0,%1},%2;" : "=f"(x), "=f"(y) : "l"(v));
    return x + y;
}
__device__ __forceinline__ unsigned long long seed2(float x) {
    return (unsigned long long)__float_as_uint(x);   // (x, +0.0f)
}
__device__ __forceinline__ float sigmf_(float x) {
    return __fdividef(1.0f, 1.0f + __expf(-x));
}
__device__ __forceinline__ float tanhsafe_(float x) {
    float a = fabsf(x);
    float e = __expf(-2.0f * a);
    float t = __fdividef(1.0f - e, 1.0f + e);
    return copysignf(t, x);
}
#define PAIRBAR(id) asm volatile("bar.sync %0, %1;" :: "r"(id), "r"(64) : "memory")

// ============================================================
// Prep: decode adj + build ordered edge lists
// ============================================================
__global__ void k_prep(const unsigned char* __restrict__ adj_raw) {
    __shared__ float sadj[Nn * Nn];
    __shared__ int s_gt1, s_off4;
    const int tid = threadIdx.x;
    if (tid == 0) { s_gt1 = 0; s_off4 = 0; }
    __syncthreads();
    int f_gt1 = 0, f_off4 = 0;
    for (int t = tid; t < Nn * Nn; t += blockDim.x) {
        unsigned char c = adj_raw[t];
        if (c > 1) f_gt1 = 1;
        if (c == 1 && (t & 3) != 0) f_off4 = 1;
    }
    if (f_gt1)  atomicOr(&s_gt1, 1);
    if (f_off4) atomicOr(&s_off4, 1);
    __syncthreads();
    const int mode = s_gt1 ? 1 : (s_off4 ? 0 : 2);
    for (int e = tid; e < Nn * Nn; e += blockDim.x) {
        float v;
        if (mode == 1)      v = ((const float*)adj_raw)[e];
        else if (mode == 2) v = (float)(((const int*)adj_raw)[e]);
        else                v = (float)adj_raw[e];
        sadj[e] = v;
    }
    __syncthreads();
    if (tid < Nn) {
        const int i = tid; int c = 0;
        for (int j = 0; j < Nn; j++)
            if (sadj[j * Nn + i] != 0.0f) g_flist[i][c++] = j;
        g_fcnt[i] = c;
    } else if (tid < 2 * Nn) {
        const int i = tid - Nn; int c = 0;
        for (int j = Nn - 1; j >= 0; j--)
            if (sadj[i * Nn + j] != 0.0f) g_blist[i][c++] = j;
        g_bcnt[i] = c;
    }
}

// ============================================================
// Main scan: 128 blocks (64 fwd, 64 bwd), 16 samples each.
// Warp-PAIR owns 4 samples; warp owns 30 dims (lane = 1 dim, 3 gate rows).
// One 64-thread named barrier per GRU step; no block barriers in scan.
// ============================================================
__global__ void __launch_bounds__(TPB, 1) k_scan(
    const float* __restrict__ has, const float* __restrict__ z, const float* __restrict__ dz,
    const float* __restrict__ Wih_f, const float* __restrict__ Whh_f,
    const float* __restrict__ bih_f, const float* __restrict__ bhh_f,
    const float* __restrict__ Wih_b, const float* __restrict__ Whh_b,
    const float* __restrict__ bih_b, const float* __restrict__ bhh_b,
    const float* __restrict__ Wfp, const float* __restrict__ bfp,
    const float* __restrict__ Wbp, const float* __restrict__ bbp)
{
    extern __shared__ __align__(16) float sm[];
    const int dir = blockIdx.x >> 6;
    const int b0  = (blockIdx.x & 63) * GPB;
    const float* Wih = dir ? Wih_b : Wih_f;
    const float* Whh = dir ? Whh_b : Whh_f;
    const float* bih = dir ? bih_b : bih_f;
    const float* bhh = dir ? bhh_b : bhh_f;
    const float* Wp  = dir ? Wbp   : Wfp;
    const float* bp  = dir ? bbp   : bfp;
    float* grho = dir ? g_rho_b : g_rho_f;
    float* gic  = dir ? g_gi_b  : g_gi_f;

    const int  tid   = threadIdx.x;
    const int  warp  = tid >> 5;
    const int  lane  = tid & 31;
    const int  pair  = warp >> 1;        // 0..3
    const int  half  = warp & 1;         // 0: dims 0-29, 1: dims 30-59
    const int  sb    = pair * 4;         // pair's sample base
    const int  lpair = half * 32 + lane; // 0..63 within pair
    const int  barid = 1 + pair;
    const bool act   = lane < 30;
    const int  d     = half * 30 + lane; // owned dim (if act)

    // ---- block-wide staging (the ONLY __syncthreads)
    for (int idx = tid; idx < 10800; idx += TPB) {
        const int r = idx / 60, c = idx - r * 60;
        sm[S_WHH + r * 68 + c] = Whh[idx];
        sm[S_WIH + r * 68 + c] = Wih[idx];
    }
    for (int idx = tid; idx < 4800; idx += TPB)
        sm[S_WF + (idx / 80) * 84 + (idx % 80)] = Wp[idx];
    for (int idx = tid; idx < 180; idx += TPB) sm[S_BIH + idx] = bih[idx];
    for (int idx = tid; idx < 60;  idx += TPB) sm[S_BF + idx]  = bp[idx];
    for (int idx = tid; idx < GPB * Nn; idx += TPB)
        sm[S_HAS + idx] = has[(size_t)(b0 + (idx >> 5)) * Nn + (idx & 31)];
    __syncthreads();

    const float bhh0 = act ? bhh[d]        : 0.0f;
    const float bhh1 = act ? bhh[60 + d]   : 0.0f;
    const float bhh2 = act ? bhh[120 + d]  : 0.0f;
    const float bih0 = act ? sm[S_BIH + d]        : 0.0f;
    const float bih1 = act ? sm[S_BIH + 60 + d]   : 0.0f;
    const float bih2 = act ? sm[S_BIH + 120 + d]  : 0.0f;

    float* sHp = sm + S_H + pair * 512;   // [buf 2][sample 4][64]
    const float* w0p = sm + S_WHH + d * 68;
    const float* w1p = sm + S_WHH + (60 + d) * 68;
    const float* w2p = sm + S_WHH + (120 + d) * 68;

    int rp = 0;
    float h_old[4];
    float gi0[4], gi1[4], gi2[4], gn0[4], gn1[4], gn2[4];
    float a0[4], a1[4], a2[4];

    // ================== node scan ==================
    for (int ii = 0; ii < Nn; ii++) {
        const int i = dir ? (Nn - 1 - ii) : ii;

        // stage this node's z/dz for the pair's samples
        for (int idx = lpair; idx < 80; idx += 64) {
            const int m = idx / 20, c = idx % 20;
            const size_t base = ((size_t)(b0 + sb + m) * Nn + i) * SE;
            sm[S_ZD + (sb + m) * 20 + c] = (c < SE) ? z[base + c] : dz[base + c - SE];
        }

        const int  cnt = dir ? g_bcnt[i] : g_fcnt[i];
        const int* lst = dir ? g_blist[i] : g_flist[i];

        #pragma unroll
        for (int m = 0; m < 4; m++) h_old[m] = 0.0f;

        if (cnt == 0) {
            if (act) {
                #pragma unroll
                for (int m = 0; m < 4; m++) sHp[rp * 256 + m * 64 + d] = 0.0f;
            }
            PAIRBAR(barid);
        } else {
            if (act) {   // e=0 gi (rows written by this same lane earlier)
                const float* gb = gic + ((size_t)lst[0] * Bsz + b0 + sb) * 180;
                #pragma unroll
                for (int m = 0; m < 4; m++) {
                    gi0[m] = gb[m * 180 + d];
                    gi1[m] = gb[m * 180 + 60 + d];
                    gi2[m] = gb[m * 180 + 120 + d];
                }
            }
            for (int e = 0; e < cnt; e++) {
                const int j = lst[e];
                if (act) {
                    if (e > 0) {
                        unsigned long long aA0[4], aB0[4], aA1[4], aB1[4], aA2[4], aB2[4];
                        #pragma unroll
                        for (int m = 0; m < 4; m++) {
                            aA0[m]=0; aB0[m]=0; aA1[m]=0; aB1[m]=0; aA2[m]=0; aB2[m]=0;
                        }
                        const float* Hb = sHp + rp * 256;
                        #pragma unroll
                        for (int q = 0; q < 15; q++) {
                            const ulonglong2 w0 = *(const ulonglong2*)(w0p + q * 4);
                            const ulonglong2 w1 = *(const ulonglong2*)(w1p + q * 4);
                            const ulonglong2 w2 = *(const ulonglong2*)(w2p + q * 4);
                            #pragma unroll
                            for (int m = 0; m < 4; m++) {
                                const ulonglong2 h = *(const ulonglong2*)(Hb + m * 64 + q * 4);
                                fma2(aA0[m], w0.x, h.x); fma2(aB0[m], w0.y, h.y);
                                fma2(aA1[m], w1.x, h.x); fma2(aB1[m], w1.y, h.y);
                                fma2(aA2[m], w2.x, h.x); fma2(aB2[m], w2.y, h.y);
                            }
                        }
                        #pragma unroll
                        for (int m = 0; m < 4; m++) {
                            a0[m] = red2(aA0[m]) + red2(aB0[m]);
                            a1[m] = red2(aA1[m]) + red2(aB1[m]);
                            a2[m] = red2(aA2[m]) + red2(aB2[m]);
                        }
                    } else {
                        #pragma unroll
                        for (int m = 0; m < 4; m++) { a0[m]=0; a1[m]=0; a2[m]=0; }
                    }
                    if (e + 1 < cnt) {   // prefetch next gi
                        const float* gb = gic + ((size_t)lst[e + 1] * Bsz + b0 + sb) * 180;
                        #pragma unroll
                        for (int m = 0; m < 4; m++) {
                            gn0[m] = gb[m * 180 + d];
                            gn1[m] = gb[m * 180 + 60 + d];
                            gn2[m] = gb[m * 180 + 120 + d];
                        }
                    }
                    #pragma unroll
                    for (int m = 0; m < 4; m++) {
                        const float mask = sm[S_HAS + (sb + m) * 32 + j];
                        const float r  = sigmf_(a0[m] + gi0[m] + bhh0);
                        const float u  = sigmf_(a1[m] + gi1[m] + bhh1);
                        const float nv = tanhsafe_(gi2[m] + r * (a2[m] + bhh2));
                        const float ho = h_old[m];
                        const float h2 = (1.0f - u) * nv + u * ho;
                        const float hn = ho + mask * (h2 - ho);
                        h_old[m] = hn;
                        sHp[(1 - rp) * 256 + m * 64 + d] = hn;
                    }
                    if (e + 1 < cnt) {
                        #pragma unroll
                        for (int m = 0; m < 4; m++) {
                            gi0[m]=gn0[m]; gi1[m]=gn1[m]; gi2[m]=gn2[m];
                        }
                    }
                }
                PAIRBAR(barid);
                rp ^= 1;
            }
        }

        // ---- projection: lane -> dim d, 4 samples (h complete after bar)
        if (act) {
            const ulonglong2* Wr = (const ulonglong2*)(sm + S_WF + d * 84);
            #pragma unroll
            for (int m = 0; m < 4; m++) {
                unsigned long long acc = seed2(sm[S_BF + d]);
                const ulonglong2* Hh = (const ulonglong2*)(sHp + rp * 256 + m * 64);
                #pragma unroll
                for (int q = 0; q < 15; q++) {
                    const ulonglong2 w = Wr[q], h = Hh[q];
                    fma2(acc, w.x, h.x); fma2(acc, w.y, h.y);
                }
                const ulonglong2* Zd = (const ulonglong2*)(sm + S_ZD + (sb + m) * 20);
                #pragma unroll
                for (int q = 0; q < 5; q++) {
                    const ulonglong2 w = Wr[15 + q], x = Zd[q];
                    fma2(acc, w.x, x.x); fma2(acc, w.y, x.y);
                }
                float val = red2(acc);
                if (dir == 0) val = tanhsafe_(val);
                sm[S_RHO + (sb + m) * 64 + d] = val;
                grho[((size_t)i * Bsz + b0 + sb + m) * 60 + d] = val;
            }
        }
        PAIRBAR(barid);   // rho complete (both halves)

        // ---- gi for node i: rows {d, 60+d, 120+d} x 4 samples (Wih in smem)
        if (act) {
            unsigned long long aA0[4], aB0[4], aA1[4], aB1[4], aA2[4], aB2[4];
            #pragma unroll
            for (int m = 0; m < 4; m++) {
                aA0[m]=seed2(bih0); aB0[m]=0;
                aA1[m]=seed2(bih1); aB1[m]=0;
                aA2[m]=seed2(bih2); aB2[m]=0;
            }
            const float* u0p = sm + S_WIH + d * 68;
            const float* u1p = sm + S_WIH + (60 + d) * 68;
            const float* u2p = sm + S_WIH + (120 + d) * 68;
            const float* Rb = sm + S_RHO + sb * 64;
            #pragma unroll
            for (int q = 0; q < 15; q++) {
                const ulonglong2 w0 = *(const ulonglong2*)(u0p + q * 4);
                const ulonglong2 w1 = *(const ulonglong2*)(u1p + q * 4);
                const ulonglong2 w2 = *(const ulonglong2*)(u2p + q * 4);
                #pragma unroll
                for (int m = 0; m < 4; m++) {
                    const ulonglong2 rv = *(const ulonglong2*)(Rb + m * 64 + q * 4);
                    fma2(aA0[m], w0.x, rv.x); fma2(aB0[m], w0.y, rv.y);
                    fma2(aA1[m], w1.x, rv.x); fma2(aB1[m], w1.y, rv.y);
                    fma2(aA2[m], w2.x, rv.x); fma2(aB2[m], w2.y, rv.y);
                }
            }
            #pragma unroll
            for (int m = 0; m < 4; m++) {
                float* gp = gic + ((size_t)i * Bsz + b0 + sb + m) * 180;
                gp[d]        = red2(aA0[m]) + red2(aB0[m]);
                gp[60 + d]   = red2(aA1[m]) + red2(aB1[m]);
                gp[120 + d]  = red2(aA2[m]) + red2(aB2[m]);
            }
        }
        PAIRBAR(barid);   // partner's gi rho-reads done before next proj overwrites
    }

    // ================== alpha scan ==================
    #pragma unroll
    for (int m = 0; m < 4; m++) h_old[m] = 0.0f;
    const int steps = dir ? IIN : OOUT;
    for (int s = 0; s < steps; s++) {
        const int i = dir ? (IIN - 1 - s) : (Nn - OOUT + s);
        if (act) {
            const float* gb = gic + ((size_t)i * Bsz + b0 + sb) * 180;
            #pragma unroll
            for (int m = 0; m < 4; m++) {
                gi0[m] = gb[m * 180 + d];
                gi1[m] = gb[m * 180 + 60 + d];
                gi2[m] = gb[m * 180 + 120 + d];
            }
            if (s > 0) {
                unsigned long long aA0[4], aB0[4], aA1[4], aB1[4], aA2[4], aB2[4];
                #pragma unroll
                for (int m = 0; m < 4; m++) {
                    aA0[m]=0; aB0[m]=0; aA1[m]=0; aB1[m]=0; aA2[m]=0; aB2[m]=0;
                }
                const float* Hb = sHp + rp * 256;
                #pragma unroll
                for (int q = 0; q < 15; q++) {
                    const ulonglong2 w0 = *(const ulonglong2*)(w0p + q * 4);
                    const ulonglong2 w1 = *(const ulonglong2*)(w1p + q * 4);
                    const ulonglong2 w2 = *(const ulonglong2*)(w2p + q * 4);
                    #pragma unroll
                    for (int m = 0; m < 4; m++) {
                        const ulonglong2 h = *(const ulonglong2*)(Hb + m * 64 + q * 4);
                        fma2(aA0[m], w0.x, h.x); fma2(aB0[m], w0.y, h.y);
                        fma2(aA1[m], w1.x, h.x); fma2(aB1[m], w1.y, h.y);
                        fma2(aA2[m], w2.x, h.x); fma2(aB2[m], w2.y, h.y);
                    }
                }
                #pragma unroll
                for (int m = 0; m < 4; m++) {
                    a0[m] = red2(aA0[m]) + red2(aB0[m]);
                    a1[m] = red2(aA1[m]) + red2(aB1[m]);
                    a2[m] = red2(aA2[m]) + red2(aB2[m]);
                }
            } else {
                #pragma unroll
                for (int m = 0; m < 4; m++) { a0[m]=0; a1[m]=0; a2[m]=0; }
            }
            #pragma unroll
            for (int m = 0; m < 4; m++) {
                const float mask = sm[S_HAS + (sb + m) * 32 + i];
                const float r  = sigmf_(a0[m] + gi0[m] + bhh0);
                const float u  = sigmf_(a1[m] + gi1[m] + bhh1);
                const float nv = tanhsafe_(gi2[m] + r * (a2[m] + bhh2));
                const float ho = h_old[m];
                const float h2 = (1.0f - u) * nv + u * ho;
                const float hn = ho + mask * (h2 - ho);
                h_old[m] = hn;
                sHp[(1 - rp) * 256 + m * 64 + d] = hn;
            }
        }
        PAIRBAR(barid);
        rp ^= 1;
    }
    if (act) {
        float* ga = dir ? g_ab : g_af;
        #pragma unroll
        for (int m = 0; m < 4; m++)
            ga[(size_t)(b0 + sb + m) * 60 + d] = h_old[m];
    }
}

// ============================================================
// Heads: blocks [0,128) role_prob; [128,144) instr_prob + value
// out: [0,5120) instr | [5120,234496) roles | [234496,235520) value
// ============================================================
__global__ void k_heads(const float* __restrict__ has,
                        const float* __restrict__ Wu, const float* __restrict__ bu,
                        const float* __restrict__ Wa, const float* __restrict__ ba,
                        const float* __restrict__ Wc, const float* __restrict__ bc,
                        float* __restrict__ out)
{
    const int tid = threadIdx.x;
    if (blockIdx.x < 128) {
        __shared__ __align__(16) float sWu[7 * 120];
        __shared__ float sbu[7];
        for (int idx = tid; idx < 840; idx += blockDim.x) sWu[idx] = Wu[idx];
        if (tid < 7) sbu[tid] = bu[tid];
        __syncthreads();

        const int t = blockIdx.x * 256 + tid;
        const int b = t >> 5;
        const int n = t & 31;

        float acc[7];
        #pragma unroll
        for (int r = 0; r < 7; r++) acc[r] = sbu[r];

        const float4* rf = (const float4*)(g_rho_f + ((size_t)n * Bsz + b) * 60);
        const float4* rb = (const float4*)(g_rho_b + ((size_t)n * Bsz + b) * 60);
        #pragma unroll
        for (int q = 0; q < 15; q++) {
            const float4 f = rf[q];
            #pragma unroll
            for (int r = 0; r < 7; r++) {
                const float4 w = *(const float4*)(sWu + r * 120 + q * 4);
                acc[r] += w.x*f.x + w.y*f.y + w.z*f.z + w.w*f.w;
            }
        }
        #pragma unroll
        for (int q = 0; q < 15; q++) {
            const float4 f = rb[q];
            #pragma unroll
            for (int r = 0; r < 7; r++) {
                const float4 w = *(const float4*)(sWu + r * 120 + 60 + q * 4);
                acc[r] += w.x*f.x + w.y*f.y + w.z*f.z + w.w*f.w;
            }
        }
        const float m = has[b * Nn + n];
        float l[7], mx = -1e30f;
        #pragma unroll
        for (int r = 0; r < 7; r++) { l[r] = (m != 0.0f) ? acc[r] : -60.0f; mx = fmaxf(mx, l[r]); }
        float s = 0.0f;
        #pragma unroll
        for (int r = 0; r < 7; r++) { l[r] = __expf(l[r] - mx); s += l[r]; }
        const float inv = __fdividef(1.0f, s);
        float* ro = out + 5120;
        #pragma unroll
        for (int r = 0; r < 7; r++) ro[((size_t)b * 7 + r) * 32 + n] = l[r] * inv;
    } else {
        __shared__ __align__(16) float sWa[5 * 120];
        __shared__ __align__(16) float sWc[120];
        __shared__ float sba[5];
        __shared__ float sbc;
        for (int idx = tid; idx < 600; idx += blockDim.x) sWa[idx] = Wa[idx];
        for (int idx = tid; idx < 120; idx += blockDim.x) sWc[idx] = Wc[idx];
        if (tid < 5) sba[tid] = ba[tid];
        if (tid == 0) sbc = bc[0];
        __syncthreads();

        const int t    = (blockIdx.x - 128) * 256 + tid;
        const int b    = t >> 2;
        const int lane = t & 3;

        float acc[6];
        #pragma unroll
        for (int a = 0; a < 6; a++) acc[a] = 0.0f;

        const float4* af = (const float4*)(g_af + (size_t)b * 60);
        const float4* ab = (const float4*)(g_ab + (size_t)b * 60);
        for (int q = lane; q < 30; q += 4) {
            const float4 f = (q < 15) ? af[q] : ab[q - 15];
            #pragma unroll
            for (int a = 0; a < 5; a++) {
                const float4 w = *(const float4*)(sWa + a * 120 + q * 4);
                acc[a] += w.x*f.x + w.y*f.y + w.z*f.z + w.w*f.w;
            }
            const float4 wc = *(const float4*)(sWc + q * 4);
            acc[5] += wc.x*f.x + wc.y*f.y + wc.z*f.z + wc.w*f.w;
        }
        #pragma unroll
        for (int off = 1; off < 4; off <<= 1) {
            #pragma unroll
            for (int a = 0; a < 6; a++)
                acc[a] += __shfl_xor_sync(0xffffffffu, acc[a], off);
        }
        if (lane == 0) {
            float l[5], mx = -1e30f;
            #pragma unroll
            for (int a = 0; a < 5; a++) { l[a] = acc[a] + sba[a]; mx = fmaxf(mx, l[a]); }
            float s = 0.0f;
            #pragma unroll
            for (int a = 0; a < 5; a++) { l[a] = __expf(l[a] - mx); s += l[a]; }
            const float inv = __fdividef(1.0f, s);
            #pragma unroll
            for (int a = 0; a < 5; a++) out[b * 5 + a] = l[a] * inv;
            out[5120 + Bsz * 7 * Nn + b] = acc[5] + sbc;   // value @ 234496
        }
    }
}

// ============================================================
extern "C" void kernel_launch(void* const* d_in, const int* in_sizes, int n_in,
                              void* d_out, int out_size)
{
    const float* has   = (const float*)d_in[0];
    const float* z     = (const float*)d_in[1];
    const float* dz    = (const float*)d_in[2];
    const unsigned char* adj = (const unsigned char*)d_in[3];
    const float* Wih_f = (const float*)d_in[4];
    const float* Whh_f = (const float*)d_in[5];
    const float* bih_f = (const float*)d_in[6];
    const float* bhh_f = (const float*)d_in[7];
    const float* Wih_b = (const float*)d_in[8];
    const float* Whh_b = (const float*)d_in[9];
    const float* bih_b = (const float*)d_in[10];
    const float* bhh_b = (const float*)d_in[11];
    const float* Wf    = (const float*)d_in[12];
    const float* bf    = (const float*)d_in[13];
    const float* Wb    = (const float*)d_in[14];
    const float* bb    = (const float*)d_in[15];
    const float* Wa    = (const float*)d_in[16];
    const float* ba    = (const float*)d_in[17];
    const float* Wc    = (const float*)d_in[18];
    const float* bc    = (const float*)d_in[19];
    const float* Wu    = (const float*)d_in[20];
    const float* bu    = (const float*)d_in[21];
    float* out = (float*)d_out;

    const size_t smem = SMEM_FLOATS * sizeof(float);   // ~132 KB -> 1 block/SM
    cudaFuncSetAttribute(k_scan, cudaFuncAttributeMaxDynamicSharedMemorySize, (int)smem);

    k_prep<<<1, 256>>>(adj);
    k_scan<<<128, TPB, smem>>>(has, z, dz,
                               Wih_f, Whh_f, bih_f, bhh_f,
                               Wih_b, Whh_b, bih_b, bhh_b,
                               Wf, bf, Wb, bb);
    k_heads<<<144, 256>>>(has, Wu, bu, Wa, ba, Wc, bc, out);
}